// round 2
// baseline (speedup 1.0000x reference)
#include <cuda_runtime.h>

#define BATCH 64
#define NPIX  196
#define C1    2048
#define C2    512
#define KCONV 18432
#define K4    4096
#define EPSF  1e-6f

// ---------------- scratch (device globals; no allocation) ----------------
__device__ float g_x [(size_t)BATCH * C2 * NPIX];   // conv+bn+relu output
__device__ float g_x2[(size_t)BATCH * C2 * NPIX];   // GCEM output
__device__ float g_zt[(size_t)BATCH * 8  * NPIX];   // attention maps
__device__ float g_x1[(size_t)BATCH * 4096 * NPIX]; // bkchv tensor
__device__ float g_t [(size_t)BATCH * C1 * NPIX];   // r5 * dic_global
__device__ float g_xb[(size_t)BATCH * C1 * NPIX];   // conv4(concat)
__device__ float g_xd[(size_t)BATCH * 32 * NPIX];   // downconv
__device__ float g_xc[(size_t)BATCH * NPIX];        // pooled attention scalar map

// ===========================================================================
// Kernel 1: conv3x3(2048->512) + BN + ReLU as implicit GEMM
// M=512, N=64*196=12544, K=18432 (k = ci*9 + kh*3 + kw)
// ===========================================================================
__global__ void __launch_bounds__(256) conv_gemm_kernel(
    const float* __restrict__ W,      // [512, 18432] row-major
    const float* __restrict__ r5,     // [64,2048,14,14]
    const float* __restrict__ gamma, const float* __restrict__ beta,
    const float* __restrict__ mean,  const float* __restrict__ var)
{
    __shared__ float As[8][128];
    __shared__ float Bs[8][128];
    const int tid = threadIdx.x;
    const int tx = tid & 15, ty = tid >> 4;
    const int m0   = blockIdx.y * 128;
    const int col0 = blockIdx.x * 128;
    const int rowA = tid >> 1, segA = (tid & 1) * 4;
    const int nB   = tid & 127, kB0 = tid >> 7;

    const int colB = col0 + nB;
    const int bB = colB / NPIX;
    const int nn = colB - bB * NPIX;
    const int hB = nn / 14, wB = nn - hB * 14;
    const float* r5b = r5 + (size_t)bB * C1 * NPIX;
    const float* Arow = W + (size_t)(m0 + rowA) * KCONV + segA;

    float acc[8][8];
#pragma unroll
    for (int i = 0; i < 8; i++)
#pragma unroll
        for (int j = 0; j < 8; j++) acc[i][j] = 0.f;

    // prefetch first tile
    float4 aReg = *(const float4*)(Arow);
    float bReg[4];
#pragma unroll
    for (int u = 0; u < 4; u++) {
        int k = kB0 + 2 * u;
        int ci = k / 9, r = k - ci * 9, kh = r / 3, kw = r - kh * 3;
        int ih = hB + kh - 1, iw = wB + kw - 1;
        bReg[u] = ((unsigned)ih < 14u && (unsigned)iw < 14u)
                      ? r5b[(ci * 14 + ih) * 14 + iw] : 0.f;
    }

    for (int kt = 0; kt < KCONV; kt += 8) {
        As[segA + 0][rowA] = aReg.x; As[segA + 1][rowA] = aReg.y;
        As[segA + 2][rowA] = aReg.z; As[segA + 3][rowA] = aReg.w;
#pragma unroll
        for (int u = 0; u < 4; u++) Bs[kB0 + 2 * u][nB] = bReg[u];
        __syncthreads();

        if (kt + 8 < KCONV) {
            aReg = *(const float4*)(Arow + kt + 8);
#pragma unroll
            for (int u = 0; u < 4; u++) {
                int k = kt + 8 + kB0 + 2 * u;
                int ci = k / 9, r = k - ci * 9, kh = r / 3, kw = r - kh * 3;
                int ih = hB + kh - 1, iw = wB + kw - 1;
                bReg[u] = ((unsigned)ih < 14u && (unsigned)iw < 14u)
                              ? r5b[(ci * 14 + ih) * 14 + iw] : 0.f;
            }
        }
#pragma unroll
        for (int k = 0; k < 8; k++) {
            float a[8], bb[8];
            *(float4*)(a)      = *(const float4*)&As[k][ty * 4];
            *(float4*)(a + 4)  = *(const float4*)&As[k][64 + ty * 4];
            *(float4*)(bb)     = *(const float4*)&Bs[k][tx * 4];
            *(float4*)(bb + 4) = *(const float4*)&Bs[k][64 + tx * 4];
#pragma unroll
            for (int i = 0; i < 8; i++)
#pragma unroll
                for (int j = 0; j < 8; j++)
                    acc[i][j] = fmaf(a[i], bb[j], acc[i][j]);
        }
        __syncthreads();
    }
#pragma unroll
    for (int i = 0; i < 8; i++) {
        int m = m0 + ((i < 4) ? ty * 4 + i : 64 + ty * 4 + i - 4);
        float sc = gamma[m] / sqrtf(var[m] + 1e-5f);
        float sh = beta[m] - mean[m] * sc;
#pragma unroll
        for (int j = 0; j < 8; j++) {
            int col = col0 + ((j < 4) ? tx * 4 + j : 64 + tx * 4 + j - 4);
            int bo = col / NPIX, n = col - bo * NPIX;
            float v = acc[i][j] * sc + sh;
            g_x[((size_t)bo * C2 + m) * NPIX + n] = fmaxf(v, 0.f);
        }
    }
}

// ===========================================================================
// Kernel 2: EM attention (stage_num=3), one block per batch
// ===========================================================================
__global__ void __launch_bounds__(256) em_kernel(const float* __restrict__ mu0)
{
    const int b = blockIdx.x;
    const int tid = threadIdx.x, lane = tid & 31, wid = tid >> 5;
    const float* xb = g_x + (size_t)b * C2 * NPIX;

    __shared__ float mu[C2 * 8];
    __shared__ float z[NPIX * 8];
    __shared__ float norm[8], colsum[8];

    { // norm of mu0 columns (warp wid -> column wid)
        float s = 0.f;
        for (int c = lane; c < C2; c += 32) { float v = mu0[c * 8 + wid]; s += v * v; }
#pragma unroll
        for (int o = 16; o; o >>= 1) s += __shfl_xor_sync(0xffffffffu, s, o);
        if (!lane) norm[wid] = sqrtf(s) + EPSF;
    }
    __syncthreads();
    for (int i = tid; i < C2 * 8; i += 256) mu[i] = mu0[i] / norm[i & 7];
    __syncthreads();

    for (int it = 0; it < 3; ++it) {
        if (tid < NPIX) {                       // logits + softmax over k
            float l[8];
#pragma unroll
            for (int k = 0; k < 8; k++) l[k] = 0.f;
            for (int c = 0; c < C2; c++) {
                float xv = xb[c * NPIX + tid];
#pragma unroll
                for (int k = 0; k < 8; k++) l[k] += xv * mu[c * 8 + k];
            }
            float mx = l[0];
#pragma unroll
            for (int k = 1; k < 8; k++) mx = fmaxf(mx, l[k]);
            float e[8], s = 0.f;
#pragma unroll
            for (int k = 0; k < 8; k++) { e[k] = expf(l[k] - mx); s += e[k]; }
            float inv = 1.f / s;
#pragma unroll
            for (int k = 0; k < 8; k++) z[tid * 8 + k] = e[k] * inv;
        }
        __syncthreads();
        {                                       // column sums of z
            float s = 0.f;
            for (int n = lane; n < NPIX; n += 32) s += z[n * 8 + wid];
#pragma unroll
            for (int o = 16; o; o >>= 1) s += __shfl_xor_sync(0xffffffffu, s, o);
            if (!lane) colsum[wid] = s + EPSF;
        }
        __syncthreads();
        for (int o = tid; o < C2 * 8; o += 256) {  // mu = x @ zn
            int c = o >> 3, k = o & 7;
            const float* xr = xb + c * NPIX;
            float s = 0.f;
            for (int n = 0; n < NPIX; n++) s += xr[n] * z[n * 8 + k];
            mu[o] = s / colsum[k];
        }
        __syncthreads();
        {                                       // normalize mu columns
            float s = 0.f;
            for (int c = lane; c < C2; c += 32) { float v = mu[c * 8 + wid]; s += v * v; }
#pragma unroll
            for (int o = 16; o; o >>= 1) s += __shfl_xor_sync(0xffffffffu, s, o);
            if (!lane) norm[wid] = sqrtf(s) + EPSF;
        }
        __syncthreads();
        for (int i = tid; i < C2 * 8; i += 256) mu[i] /= norm[i & 7];
        __syncthreads();
    }
    if (tid < NPIX) {                           // x2 = relu(x + mu @ z^T), emit z_t
        float zr[8];
#pragma unroll
        for (int k = 0; k < 8; k++) zr[k] = z[tid * 8 + k];
        float* x2o = g_x2 + (size_t)b * C2 * NPIX;
        for (int c = 0; c < C2; c++) {
            float s = 0.f;
#pragma unroll
            for (int k = 0; k < 8; k++) s += mu[c * 8 + k] * zr[k];
            float v = xb[c * NPIX + tid] + s;
            x2o[c * NPIX + tid] = fmaxf(v, 0.f);
        }
#pragma unroll
        for (int k = 0; k < 8; k++) g_zt[((size_t)b * 8 + k) * NPIX + tid] = zr[k];
    }
}

// ===========================================================================
// Kernel 3: x1[b, k*512+c, h, v] = sum_w x2[b,c,h,w] * zt[b,k,w,v]
// ===========================================================================
__global__ void __launch_bounds__(256) x1_kernel()
{
    const int b = blockIdx.x, tid = threadIdx.x;
    __shared__ float zts[8 * NPIX];
    for (int i = tid; i < 8 * NPIX; i += 256) zts[i] = g_zt[(size_t)b * 8 * NPIX + i];
    __syncthreads();
    const float* x2b = g_x2 + (size_t)b * C2 * NPIX;
    float* x1b = g_x1 + (size_t)b * 4096 * NPIX;
    for (int r = tid; r < C2 * 14; r += 256) {
        int c = r / 14, h = r - c * 14;
        float xv[14];
        const float* xp = x2b + c * NPIX + h * 14;
#pragma unroll
        for (int w = 0; w < 14; w++) xv[w] = xp[w];
        for (int k = 0; k < 8; k++) {
            float out[14];
#pragma unroll
            for (int v = 0; v < 14; v++) out[v] = 0.f;
#pragma unroll
            for (int w = 0; w < 14; w++) {
                float a = xv[w];
                const float* zp = zts + k * NPIX + w * 14;
#pragma unroll
                for (int v = 0; v < 14; v++) out[v] += a * zp[v];
            }
            float* op = x1b + ((size_t)k * C2 + c) * NPIX + h * 14;
#pragma unroll
            for (int v = 0; v < 14; v++) op[v] = out[v];
        }
    }
}

// ===========================================================================
// Kernel 4/5: conv4 GEMM, M=2048, N=12544, K=4096
// MODE 0: B = x1,        out: g_t  = r5 * (acc + bias)
// MODE 1: B = [t ; r5],  out: g_xb = acc + bias
// ===========================================================================
template <int MODE>
__device__ __forceinline__ float gatherB(int k, const float* x1b,
                                         const float* tb, const float* r5b)
{
    if (MODE == 0) return x1b[(size_t)k * NPIX];
    return (k < 2048) ? tb[(size_t)k * NPIX] : r5b[(size_t)(k - 2048) * NPIX];
}

template <int MODE>
__global__ void __launch_bounds__(256) gemm4096_kernel(
    const float* __restrict__ A, const float* __restrict__ bias,
    const float* __restrict__ r5)
{
    __shared__ float As[8][128];
    __shared__ float Bs[8][128];
    const int tid = threadIdx.x;
    const int tx = tid & 15, ty = tid >> 4;
    const int m0 = blockIdx.y * 128, col0 = blockIdx.x * 128;
    const int rowA = tid >> 1, segA = (tid & 1) * 4;
    const int nB = tid & 127, kB0 = tid >> 7;

    const int colB = col0 + nB;
    const int bB = colB / NPIX;
    const int nn = colB - bB * NPIX;
    const float* x1b = g_x1 + (size_t)bB * 4096 * NPIX + nn;
    const float* tb  = g_t  + (size_t)bB * C1 * NPIX + nn;
    const float* r5b = r5   + (size_t)bB * C1 * NPIX + nn;
    const float* Arow = A + (size_t)(m0 + rowA) * K4 + segA;

    float acc[8][8];
#pragma unroll
    for (int i = 0; i < 8; i++)
#pragma unroll
        for (int j = 0; j < 8; j++) acc[i][j] = 0.f;

    float4 aReg = *(const float4*)(Arow);
    float bReg[4];
#pragma unroll
    for (int u = 0; u < 4; u++) bReg[u] = gatherB<MODE>(kB0 + 2 * u, x1b, tb, r5b);

    for (int kt = 0; kt < K4; kt += 8) {
        As[segA + 0][rowA] = aReg.x; As[segA + 1][rowA] = aReg.y;
        As[segA + 2][rowA] = aReg.z; As[segA + 3][rowA] = aReg.w;
#pragma unroll
        for (int u = 0; u < 4; u++) Bs[kB0 + 2 * u][nB] = bReg[u];
        __syncthreads();
        if (kt + 8 < K4) {
            aReg = *(const float4*)(Arow + kt + 8);
#pragma unroll
            for (int u = 0; u < 4; u++)
                bReg[u] = gatherB<MODE>(kt + 8 + kB0 + 2 * u, x1b, tb, r5b);
        }
#pragma unroll
        for (int k = 0; k < 8; k++) {
            float a[8], bb[8];
            *(float4*)(a)      = *(const float4*)&As[k][ty * 4];
            *(float4*)(a + 4)  = *(const float4*)&As[k][64 + ty * 4];
            *(float4*)(bb)     = *(const float4*)&Bs[k][tx * 4];
            *(float4*)(bb + 4) = *(const float4*)&Bs[k][64 + tx * 4];
#pragma unroll
            for (int i = 0; i < 8; i++)
#pragma unroll
                for (int j = 0; j < 8; j++)
                    acc[i][j] = fmaf(a[i], bb[j], acc[i][j]);
        }
        __syncthreads();
    }
#pragma unroll
    for (int i = 0; i < 8; i++) {
        int m = m0 + ((i < 4) ? ty * 4 + i : 64 + ty * 4 + i - 4);
        float bi = bias[m];
#pragma unroll
        for (int j = 0; j < 8; j++) {
            int col = col0 + ((j < 4) ? tx * 4 + j : 64 + tx * 4 + j - 4);
            int bo = col / NPIX, n = col - bo * NPIX;
            size_t oidx = ((size_t)bo * C1 + m) * NPIX + n;
            float v = acc[i][j] + bi;
            if (MODE == 0) g_t[oidx] = r5[oidx] * v;
            else           g_xb[oidx] = v;
        }
    }
}

// ===========================================================================
// Kernel 6: downconv 2048->32 (4 output channels per block)
// ===========================================================================
__global__ void __launch_bounds__(256) down_kernel(
    const float* __restrict__ dw, const float* __restrict__ db)
{
    const int b = blockIdx.x, jg = blockIdx.y, tid = threadIdx.x;
    __shared__ float ws[4 * 2048];
    for (int i = tid; i < 4 * 2048; i += 256) ws[i] = dw[jg * 4 * 2048 + i];
    __syncthreads();
    if (tid < NPIX) {
        float acc[4];
#pragma unroll
        for (int j = 0; j < 4; j++) acc[j] = db[jg * 4 + j];
        const float* xp = g_xb + (size_t)b * C1 * NPIX + tid;
        for (int c = 0; c < 2048; c++) {
            float v = xp[(size_t)c * NPIX];
#pragma unroll
            for (int j = 0; j < 4; j++) acc[j] += ws[j * 2048 + c] * v;
        }
#pragma unroll
        for (int j = 0; j < 4; j++)
            g_xd[((size_t)b * 32 + jg * 4 + j) * NPIX + tid] = acc[j];
    }
}

// ===========================================================================
// Kernel 7: GAP + class-wise pools -> xg (output[0:512]) and xc map
// ===========================================================================
__global__ void __launch_bounds__(256) pool_kernel(float* __restrict__ dout)
{
    const int b = blockIdx.x, tid = threadIdx.x;
    __shared__ float gap[32];
    __shared__ float xgs[8];
    if (tid < 32) {
        const float* p = g_xd + ((size_t)b * 32 + tid) * NPIX;
        float s = 0.f;
        for (int n = 0; n < NPIX; n++) s += p[n];
        gap[tid] = s * (1.f / NPIX);
    }
    __syncthreads();
    if (tid < 8) {
        float g = 0.25f * (gap[4 * tid] + gap[4 * tid + 1] + gap[4 * tid + 2] + gap[4 * tid + 3]);
        xgs[tid] = g;
        dout[b * 8 + tid] = g;            // first output: xg
    }
    __syncthreads();
    if (tid < NPIX) {
        const float* p = g_xd + (size_t)b * 32 * NPIX + tid;
        float s = 0.f;
#pragma unroll
        for (int pp = 0; pp < 8; pp++) {
            float cp = 0.25f * (p[(4 * pp + 0) * NPIX] + p[(4 * pp + 1) * NPIX] +
                                p[(4 * pp + 2) * NPIX] + p[(4 * pp + 3) * NPIX]);
            s += cp * xgs[pp];
        }
        g_xc[b * NPIX + tid] = s * 0.125f;
    }
}

// ===========================================================================
// Kernel 8: cls head -> out2 (output[512:1024])
// ===========================================================================
__global__ void __launch_bounds__(256) out2_kernel(
    const float* __restrict__ r5, const float* __restrict__ cw,
    const float* __restrict__ cb, float* __restrict__ dout)
{
    const int b = blockIdx.x, tid = threadIdx.x, lane = tid & 31, wid = tid >> 5;
    __shared__ float xcs[NPIX];
    for (int i = tid; i < NPIX; i += 256) xcs[i] = g_xc[b * NPIX + i];
    __syncthreads();
    const float inv = 1.f / NPIX;
    float accL = 0.f;                         // lane o<8 accumulates class o
    for (int c = wid; c < 2048; c += 8) {
        const float* rp = r5 + ((size_t)b * C1 + c) * NPIX;
        float s1 = 0.f, s2 = 0.f;
        for (int n = lane; n < NPIX; n += 32) { float v = rp[n]; s1 += v; s2 += v * xcs[n]; }
#pragma unroll
        for (int o = 16; o; o >>= 1) {
            s1 += __shfl_xor_sync(0xffffffffu, s1, o);
            s2 += __shfl_xor_sync(0xffffffffu, s2, o);
        }
        if (lane < 8)
            accL += cw[lane * 4096 + c] * s1 * inv + cw[lane * 4096 + 2048 + c] * s2 * inv;
    }
    __shared__ float wsum[8][8];
    if (lane < 8) wsum[wid][lane] = accL;
    __syncthreads();
    if (tid < 8) {
        float s = cb[tid];
#pragma unroll
        for (int w2 = 0; w2 < 8; w2++) s += wsum[w2][tid];
        dout[512 + b * 8 + tid] = s;
    }
}

// ===========================================================================
extern "C" void kernel_launch(void* const* d_in, const int* in_sizes, int n_in,
                              void* d_out, int out_size)
{
    const float* r5   = (const float*)d_in[0];
    const float* fc0  = (const float*)d_in[1];
    const float* bng  = (const float*)d_in[2];
    const float* bnb  = (const float*)d_in[3];
    const float* bnm  = (const float*)d_in[4];
    const float* bnv  = (const float*)d_in[5];
    const float* mu0  = (const float*)d_in[6];
    const float* c4w  = (const float*)d_in[7];
    const float* c4b  = (const float*)d_in[8];
    const float* dw   = (const float*)d_in[9];
    const float* db   = (const float*)d_in[10];
    const float* cw   = (const float*)d_in[11];
    const float* cb   = (const float*)d_in[12];
    float* out = (float*)d_out;

    conv_gemm_kernel<<<dim3(98, 4), 256>>>(fc0, r5, bng, bnb, bnm, bnv);
    em_kernel<<<64, 256>>>(mu0);
    x1_kernel<<<64, 256>>>();
    gemm4096_kernel<0><<<dim3(98, 16), 256>>>(c4w, c4b, r5);
    gemm4096_kernel<1><<<dim3(98, 16), 256>>>(c4w, c4b, r5);
    down_kernel<<<dim3(64, 8), 256>>>(dw, db);
    pool_kernel<<<64, 256>>>(out);
    out2_kernel<<<64, 256>>>(r5, cw, cb, out);
}